// round 1
// baseline (speedup 1.0000x reference)
#include <cuda_runtime.h>
#include <cuda_bf16.h>
#include <math.h>

// ---------------------------------------------------------------------------
// Scratch (device globals — no allocation allowed)
// ---------------------------------------------------------------------------
__device__ float g_Uk[128 * 128];   // effective x->hk weights
__device__ float g_Uq[128 * 128];   // effective x->hq weights
__device__ float g_ck[128];         // effective hk bias
__device__ float g_cq[128];         // effective hq bias
__device__ float g_hk[2048 * 128];  // hk for all rows (B*N, NH*32)
__device__ float g_hq[2048 * 128];
__device__ float g_c[2048 * 640];   // concat buffer [v | o0 | o1 | o2 | o3]
__device__ float g_h1[2048 * 256];  // decoder hidden

// ---------------------------------------------------------------------------
// prep: Uk[d, h*32+a] = sum_t Wk[d, h*32+t] * Wa1[t, a]       (Wa1_k rows 0..31)
//       Uq[d, h*32+a] = sum_t Wq[d, h*32+t] * Wa1[32+t, a]    (Wa1_q rows 32..63)
//       ck[h*32+a]    = sum_t bk[h*32+t]  * Wa1[t, a]   (same for cq)
// ---------------------------------------------------------------------------
__global__ __launch_bounds__(256) void prep_kernel(
    const float* __restrict__ Wk, const float* __restrict__ bk,
    const float* __restrict__ Wq, const float* __restrict__ bq,
    const float* __restrict__ Wa1)
{
    __shared__ float wa[64 * 32];
    int tid = threadIdx.x;
    for (int i = tid; i < 64 * 32; i += 256) wa[i] = Wa1[i];
    __syncthreads();

    int stride = gridDim.x * 256;
    for (int idx = blockIdx.x * 256 + tid; idx < 128 * 128; idx += stride) {
        int d = idx >> 7;
        int j = idx & 127;
        int hb = (j >> 5) << 5;   // head base column
        int a = j & 31;
        float sk = 0.f, sq = 0.f;
        #pragma unroll
        for (int t = 0; t < 32; t++) {
            sk += Wk[d * 128 + hb + t] * wa[t * 32 + a];
            sq += Wq[d * 128 + hb + t] * wa[(32 + t) * 32 + a];
        }
        g_Uk[idx] = sk;
        g_Uq[idx] = sq;
    }
    if (blockIdx.x == 0) {
        for (int idx = tid; idx < 128; idx += 256) {
            int hb = (idx >> 5) << 5;
            int a = idx & 31;
            float sk = 0.f, sq = 0.f;
            #pragma unroll
            for (int t = 0; t < 32; t++) {
                sk += bk[hb + t] * wa[t * 32 + a];
                sq += bq[hb + t] * wa[(32 + t) * 32 + a];
            }
            g_ck[idx] = sk;
            g_cq[idx] = sq;
        }
    }
}

// ---------------------------------------------------------------------------
// Generic tiled GEMM: C[m, n] = act( sum_k A[m,k] * W[k,n] + bias[n] )
// Tile 64x64, K-chunk 32, 256 threads, 4x4 micro-tile per thread.
// M, N multiples of 64; K multiple of 32 (all shapes here satisfy this).
// ---------------------------------------------------------------------------
template <bool RELU>
__global__ __launch_bounds__(256) void gemm_kernel(
    const float* __restrict__ A, int lda,
    const float* __restrict__ W, int ldw,
    const float* __restrict__ bias,
    float* __restrict__ C, int ldc,
    int K)
{
    __shared__ float As[32][65];   // [k][m] transposed, padded
    __shared__ float Ws[32][64];   // [k][n]

    int tid = threadIdx.x;
    int tx = tid & 15;        // 16 col-groups of 4
    int ty = tid >> 4;        // 16 row-groups of 4
    int m0 = blockIdx.y * 64;
    int n0 = blockIdx.x * 64;

    float acc[4][4] = {};

    for (int k0 = 0; k0 < K; k0 += 32) {
        #pragma unroll
        for (int s = 0; s < 8; s++) {
            int idx = tid + s * 256;          // 2048 elements of A tile
            int c = idx & 31, r = idx >> 5;
            As[c][r] = A[(size_t)(m0 + r) * lda + k0 + c];
        }
        #pragma unroll
        for (int s = 0; s < 8; s++) {
            int idx = tid + s * 256;          // 2048 elements of W tile
            int j = idx & 63, c = idx >> 6;
            Ws[c][j] = W[(size_t)(k0 + c) * ldw + n0 + j];
        }
        __syncthreads();
        #pragma unroll
        for (int kk = 0; kk < 32; kk++) {
            float a[4], b[4];
            #pragma unroll
            for (int i = 0; i < 4; i++) a[i] = As[kk][ty * 4 + i];
            #pragma unroll
            for (int j = 0; j < 4; j++) b[j] = Ws[kk][tx * 4 + j];
            #pragma unroll
            for (int i = 0; i < 4; i++)
                #pragma unroll
                for (int j = 0; j < 4; j++)
                    acc[i][j] += a[i] * b[j];
        }
        __syncthreads();
    }

    #pragma unroll
    for (int i = 0; i < 4; i++) {
        #pragma unroll
        for (int j = 0; j < 4; j++) {
            float v = acc[i][j] + bias[n0 + tx * 4 + j];
            if (RELU) v = fmaxf(v, 0.f);
            C[(size_t)(m0 + ty * 4 + i) * ldc + n0 + tx * 4 + j] = v;
        }
    }
}

// ---------------------------------------------------------------------------
// Attention kernel: for one (batch, head, 64-row i-tile):
//   s[i,j] = ba2 + sum_a relu(hk[i,a] + hq[j,a] + ba1[a]) * Wa2[a]
//   w = sigmoid(s - 10000*(i==j))
//   out[i, :] = sum_j w[i,j] * v[j, :]
// v is read from g_c cols [0,128); output written to g_c cols 128 + head*128.
// Thread layout: 256 threads = 64 rows x 4 col-groups (32 out-cols each).
// j processed in tiles of 32.
// ---------------------------------------------------------------------------
__global__ __launch_bounds__(256) void attn_kernel(
    const float* __restrict__ hk, const float* __restrict__ hq,
    float* __restrict__ cbuf,
    const float* __restrict__ ba1, const float* __restrict__ Wa2,
    const float* __restrict__ ba2)
{
    __shared__ float hk_s[64][33];
    __shared__ float hq_s[32][33];
    __shared__ float v_s[32][128];
    __shared__ float w_s[64][33];
    __shared__ float sba1[32], swa2[32];

    int tid = threadIdx.x;
    int itile = blockIdx.x;   // 0..15
    int head = blockIdx.y;    // 0..3
    int bb = blockIdx.z;      // 0..1
    int mbase = bb * 1024 + itile * 64;   // global row of first i

    int r = tid >> 2;         // 0..63  (row within tile)
    int cg = tid & 3;         // 0..3   (32-col group of v/out)

    if (tid < 32) { sba1[tid] = ba1[tid]; swa2[tid] = Wa2[tid]; }
    #pragma unroll
    for (int s = 0; s < 8; s++) {
        int idx = tid + s * 256;          // 64x32 hk tile
        int a = idx & 31, rr = idx >> 5;
        hk_s[rr][a] = hk[(size_t)(mbase + rr) * 128 + head * 32 + a];
    }
    __syncthreads();

    float rkb[32];
    #pragma unroll
    for (int a = 0; a < 32; a++) rkb[a] = hk_s[r][a] + sba1[a];
    float ba2v = ba2[0];

    float acc[32];
    #pragma unroll
    for (int d = 0; d < 32; d++) acc[d] = 0.f;

    int iloc = itile * 64 + r;   // batch-local row index

    for (int jt = 0; jt < 1024 / 32; jt++) {
        int jbase = bb * 1024 + jt * 32;
        __syncthreads();   // previous iteration's wv done before overwrite
        #pragma unroll
        for (int s = 0; s < 4; s++) {
            int idx = tid + s * 256;      // 32x32 hq tile
            int a = idx & 31, rr = idx >> 5;
            hq_s[rr][a] = hq[(size_t)(jbase + rr) * 128 + head * 32 + a];
        }
        #pragma unroll
        for (int s = 0; s < 4; s++) {
            int idx = tid + s * 256;      // 32x128 v tile as float4
            int c4 = idx & 31, rr = idx >> 5;
            const float4* src =
                (const float4*)(cbuf + (size_t)(jbase + rr) * 640) + c4;
            ((float4*)v_s[rr])[c4] = *src;
        }
        __syncthreads();

        // scores: 8 per thread (jj = cg*8 + t)
        #pragma unroll
        for (int t = 0; t < 8; t++) {
            int jj = cg * 8 + t;
            float s = ba2v;
            #pragma unroll
            for (int a = 0; a < 32; a++) {
                float u = rkb[a] + hq_s[jj][a];
                s += fmaxf(u, 0.f) * swa2[a];
            }
            int jloc = jt * 32 + jj;
            if (jloc == iloc) s -= 10000.f;
            w_s[r][jj] = 1.f / (1.f + __expf(-s));
        }
        __syncthreads();

        // wv accumulate
        #pragma unroll
        for (int jj = 0; jj < 32; jj++) {
            float w = w_s[r][jj];
            #pragma unroll
            for (int d = 0; d < 32; d++)
                acc[d] += w * v_s[jj][cg * 32 + d];
        }
    }

    float* dst = cbuf + (size_t)(mbase + r) * 640 + 128 + head * 128 + cg * 32;
    #pragma unroll
    for (int d = 0; d < 32; d++) dst[d] = acc[d];
}

// ---------------------------------------------------------------------------
// launch
// ---------------------------------------------------------------------------
extern "C" void kernel_launch(void* const* d_in, const int* in_sizes, int n_in,
                              void* d_out, int out_size)
{
    const float* x   = (const float*)d_in[0];
    const float* Wk  = (const float*)d_in[1];
    const float* bk  = (const float*)d_in[2];
    const float* Wq  = (const float*)d_in[3];
    const float* bq  = (const float*)d_in[4];
    const float* Wv  = (const float*)d_in[5];
    const float* bv  = (const float*)d_in[6];
    const float* Wa1 = (const float*)d_in[7];
    const float* ba1 = (const float*)d_in[8];
    const float* Wa2 = (const float*)d_in[9];
    const float* ba2 = (const float*)d_in[10];
    const float* Wd1 = (const float*)d_in[11];
    const float* bd1 = (const float*)d_in[12];
    const float* Wd2 = (const float*)d_in[13];
    const float* bd2 = (const float*)d_in[14];
    float* out = (float*)d_out;

    float *pUk, *pUq, *pck, *pcq, *phk, *phq, *pc, *ph1;
    cudaGetSymbolAddress((void**)&pUk, g_Uk);
    cudaGetSymbolAddress((void**)&pUq, g_Uq);
    cudaGetSymbolAddress((void**)&pck, g_ck);
    cudaGetSymbolAddress((void**)&pcq, g_cq);
    cudaGetSymbolAddress((void**)&phk, g_hk);
    cudaGetSymbolAddress((void**)&phq, g_hq);
    cudaGetSymbolAddress((void**)&pc,  g_c);
    cudaGetSymbolAddress((void**)&ph1, g_h1);

    // 1. effective weights
    prep_kernel<<<16, 256>>>(Wk, bk, Wq, bq, Wa1);

    // 2. hk = x @ Uk + ck    (M=2048, N=128, K=128)
    gemm_kernel<false><<<dim3(2, 32), 256>>>(x, 128, pUk, 128, pck, phk, 128, 128);
    // 3. hq = x @ Uq + cq
    gemm_kernel<false><<<dim3(2, 32), 256>>>(x, 128, pUq, 128, pcq, phq, 128, 128);
    // 4. v = x @ Wv + bv  -> directly into concat buffer cols [0,128)
    gemm_kernel<false><<<dim3(2, 32), 256>>>(x, 128, Wv, 128, bv, pc, 640, 128);

    // 5. attention: writes cols [128, 640) of c
    attn_kernel<<<dim3(16, 4, 2), 256>>>(phk, phq, pc, ba1, Wa2, ba2);

    // 6. h1 = relu(c @ Wd1 + bd1)   (M=2048, N=256, K=640)
    gemm_kernel<true><<<dim3(4, 32), 256>>>(pc, 640, Wd1, 256, bd1, ph1, 256, 640);
    // 7. out = h1 @ Wd2 + bd2       (M=2048, N=128, K=256)
    gemm_kernel<false><<<dim3(2, 32), 256>>>(ph1, 256, Wd2, 128, bd2, out, 128, 256);
}

// round 2
// speedup vs baseline: 3.1765x; 3.1765x over previous
#include <cuda_runtime.h>

// ---------------------------------------------------------------------------
// Scratch (device globals — no allocation allowed)
// ---------------------------------------------------------------------------
__device__ float g_Wall[128 * 384];   // [Uk | Uq | Wv]   (row-major, ld=384)
__device__ float g_ball[384];         // [ck+ba1 | cq | bv]
__device__ float g_hkq[2048 * 256];   // [hk | hq] per row
__device__ float g_c[2048 * 640];     // concat buffer [v | o0 | o1 | o2 | o3]
__device__ float g_h1[2048 * 256];    // decoder hidden

// ---------------------------------------------------------------------------
// helpers: packed f32x2 math (sm_100+)
// ---------------------------------------------------------------------------
__device__ __forceinline__ unsigned long long pack2(float lo, float hi) {
    unsigned long long r;
    asm("mov.b64 %0, {%1, %2};" : "=l"(r) : "f"(lo), "f"(hi));
    return r;
}
__device__ __forceinline__ void unpack2(unsigned long long v, float& lo, float& hi) {
    asm("mov.b64 {%0, %1}, %2;" : "=f"(lo), "=f"(hi) : "l"(v));
}
__device__ __forceinline__ unsigned long long fma2(unsigned long long a,
                                                   unsigned long long b,
                                                   unsigned long long c) {
    unsigned long long d;
    asm("fma.rn.f32x2 %0, %1, %2, %3;" : "=l"(d) : "l"(a), "l"(b), "l"(c));
    return d;
}
__device__ __forceinline__ float fast_sigmoid(float s) {
    float e = __expf(-s);          // s - 10000 on diag -> e = inf -> result 0
    float d = 1.f + e;
    float r;
    asm("rcp.approx.f32 %0, %1;" : "=f"(r) : "f"(d));
    return r;
}

// ---------------------------------------------------------------------------
// prep: build fused weight matrix [Uk | Uq | Wv] and fused bias.
//   Uk[d, h*32+a] = sum_t Wk[d, h*32+t] * Wa1[t, a]
//   Uq[d, h*32+a] = sum_t Wq[d, h*32+t] * Wa1[32+t, a]
//   bias: ck + ba1 (fold attention bias into hk), cq, bv
// ---------------------------------------------------------------------------
__global__ __launch_bounds__(256) void prep_kernel(
    const float* __restrict__ Wk, const float* __restrict__ bk,
    const float* __restrict__ Wq, const float* __restrict__ bq,
    const float* __restrict__ Wv, const float* __restrict__ bv,
    const float* __restrict__ Wa1, const float* __restrict__ ba1)
{
    __shared__ float wa[64 * 32];
    int tid = threadIdx.x;
    for (int i = tid; i < 64 * 32; i += 256) wa[i] = Wa1[i];
    __syncthreads();

    int stride = gridDim.x * 256;
    for (int idx = blockIdx.x * 256 + tid; idx < 128 * 128; idx += stride) {
        int d = idx >> 7, j = idx & 127;
        int hb = j & ~31, a = j & 31;
        float sk = 0.f, sq = 0.f;
        #pragma unroll
        for (int t = 0; t < 32; t++) {
            sk += Wk[d * 128 + hb + t] * wa[t * 32 + a];
            sq += Wq[d * 128 + hb + t] * wa[(32 + t) * 32 + a];
        }
        g_Wall[d * 384 + j]       = sk;
        g_Wall[d * 384 + 128 + j] = sq;
        g_Wall[d * 384 + 256 + j] = Wv[d * 128 + j];
    }
    if (blockIdx.x == 0 && tid < 128) {
        int hb = tid & ~31, a = tid & 31;
        float sk = 0.f, sq = 0.f;
        #pragma unroll
        for (int t = 0; t < 32; t++) {
            sk += bk[hb + t] * wa[t * 32 + a];
            sq += bq[hb + t] * wa[(32 + t) * 32 + a];
        }
        g_ball[tid]       = sk + ba1[a];   // ba1 folded into hk bias
        g_ball[128 + tid] = sq;
        g_ball[256 + tid] = bv[tid];
    }
}

// ---------------------------------------------------------------------------
// GEMM: C = act(A @ W + bias).  Tile 64x64, K-chunk 32, 256 threads,
// 4x4 micro-tile, f32x2 packed FMA.  Output router: columns < nsplit go to
// C1/ldc1, the rest to C2/ldc2 (used to fuse [hk|hq] and v outputs).
// ---------------------------------------------------------------------------
template <bool RELU>
__global__ __launch_bounds__(256) void gemm64(
    const float* __restrict__ A, int lda,
    const float* __restrict__ W, int ldw,
    const float* __restrict__ bias,
    float* __restrict__ C1, int ldc1,
    float* __restrict__ C2, int ldc2, int nsplit,
    int K)
{
    __shared__ float As[64][36];   // [m][k], pad 36 keeps 16B align + spreads banks
    __shared__ float Ws[32][64];   // [k][n]

    int tid = threadIdx.x;
    int tx = tid & 15, ty = tid >> 4;
    int m0 = blockIdx.y * 64, n0 = blockIdx.x * 64;

    unsigned long long acc2[4][2];
    #pragma unroll
    for (int i = 0; i < 4; i++) { acc2[i][0] = 0ULL; acc2[i][1] = 0ULL; }

    for (int k0 = 0; k0 < K; k0 += 32) {
        #pragma unroll
        for (int s = 0; s < 2; s++) {
            int lin = tid + s * 256;          // 512 float4 of A tile
            int m = lin >> 3, k4 = lin & 7;
            float4 f = *(const float4*)(A + (size_t)(m0 + m) * lda + k0 + k4 * 4);
            *(float4*)&As[m][k4 * 4] = f;
        }
        #pragma unroll
        for (int s = 0; s < 2; s++) {
            int lin = tid + s * 256;          // 512 float4 of W tile
            int n4 = lin & 15, kk = lin >> 4;
            float4 f = *(const float4*)(W + (size_t)(k0 + kk) * ldw + n0 + n4 * 4);
            *(float4*)&Ws[kk][n4 * 4] = f;
        }
        __syncthreads();
        #pragma unroll
        for (int kk = 0; kk < 32; kk++) {
            float4 b = *(const float4*)&Ws[kk][tx * 4];
            unsigned long long bp0 = pack2(b.x, b.y);
            unsigned long long bp1 = pack2(b.z, b.w);
            #pragma unroll
            for (int i = 0; i < 4; i++) {
                float a = As[ty * 4 + i][kk];
                unsigned long long ap = pack2(a, a);
                acc2[i][0] = fma2(ap, bp0, acc2[i][0]);
                acc2[i][1] = fma2(ap, bp1, acc2[i][1]);
            }
        }
        __syncthreads();
    }

    float4 bv4 = *(const float4*)(bias + n0 + tx * 4);
    float* Cp; int ldc;
    if (n0 < nsplit) { Cp = C1 + n0; ldc = ldc1; }
    else             { Cp = C2 + (n0 - nsplit); ldc = ldc2; }

    #pragma unroll
    for (int i = 0; i < 4; i++) {
        float o0, o1, o2, o3;
        unpack2(acc2[i][0], o0, o1);
        unpack2(acc2[i][1], o2, o3);
        o0 += bv4.x; o1 += bv4.y; o2 += bv4.z; o3 += bv4.w;
        if (RELU) {
            o0 = fmaxf(o0, 0.f); o1 = fmaxf(o1, 0.f);
            o2 = fmaxf(o2, 0.f); o3 = fmaxf(o3, 0.f);
        }
        *(float4*)(Cp + (size_t)(m0 + ty * 4 + i) * ldc + tx * 4) =
            make_float4(o0, o1, o2, o3);
    }
}

// ---------------------------------------------------------------------------
// Attention: block = (32-row i-tile, head, batch).  grid (32, 4, 2) = 256.
//   s[i,j] = ba2 + sum_a relu(hk'[i,a] + hq[j,a]) * Wa2[a]   (ba1 in hk')
//   w = sigmoid(s - 10000*(i==j)),  out[i,:] += w[i,j] * v[j,:]
// 256 threads: tx = j/d group (16), ty = i group (16). 2i x 2j score tile,
// 2i x 8d wv tile (d = tx*4 and 64+tx*4), f32x2 packed wv.
// ---------------------------------------------------------------------------
__global__ __launch_bounds__(256) void attn_kernel(
    const float* __restrict__ hkq,
    float* __restrict__ cbuf,
    const float* __restrict__ Wa2,
    const float* __restrict__ ba2)
{
    __shared__ float hk_s[8][32][4];   // [a4][i][4]
    __shared__ float hq_s[8][32][4];   // [a4][j][4]
    __shared__ float v_s[32][128];     // [j][d]
    __shared__ float w_s[32][33];      // [j][i]  (pad 33)
    __shared__ float wa2_s[32];

    int tid = threadIdx.x;
    int it = blockIdx.x, head = blockIdx.y, bb = blockIdx.z;
    int mbase = bb * 1024 + it * 32;
    int tx = tid & 15, ty = tid >> 4;

    if (tid < 32) wa2_s[tid] = Wa2[tid];
    {   // hk tile (once per block): 32 rows x 32 a
        int i = tid & 31, a4 = tid >> 5;
        float4 f = *(const float4*)(hkq + (size_t)(mbase + i) * 256 + head * 32 + a4 * 4);
        *(float4*)hk_s[a4][i] = f;
    }
    float ba2v = ba2[0];

    unsigned long long acc2[2][4];     // [ui][pair]: pairs (tx*4), (64+tx*4)
    #pragma unroll
    for (int u = 0; u < 2; u++)
        #pragma unroll
        for (int e = 0; e < 4; e++) acc2[u][e] = 0ULL;

    for (int jt = 0; jt < 32; jt++) {
        int jbase = bb * 1024 + jt * 32;
        __syncthreads();   // protect hq_s/v_s (and first-iter hk_s) before overwrite
        {
            int j = tid & 31, a4 = tid >> 5;
            float4 f = *(const float4*)(hkq + (size_t)(jbase + j) * 256 + 128 + head * 32 + a4 * 4);
            *(float4*)hq_s[a4][j] = f;
        }
        #pragma unroll
        for (int s = 0; s < 4; s++) {
            int lin = tid + s * 256;
            int j = lin >> 5, d4 = lin & 31;
            float4 f = *(const float4*)(cbuf + (size_t)(jbase + j) * 640 + d4 * 4);
            *(float4*)&v_s[j][d4 * 4] = f;
        }
        __syncthreads();

        // ---- scores (2i x 2j) ----
        float s00 = ba2v, s01 = ba2v, s10 = ba2v, s11 = ba2v;
        #pragma unroll
        for (int a4 = 0; a4 < 8; a4++) {
            float4 k0 = *(const float4*)hk_s[a4][ty * 2 + 0];
            float4 k1 = *(const float4*)hk_s[a4][ty * 2 + 1];
            float4 q0 = *(const float4*)hq_s[a4][tx * 2 + 0];
            float4 q1 = *(const float4*)hq_s[a4][tx * 2 + 1];
            float4 w4 = *(const float4*)&wa2_s[a4 * 4];
            s00 += fmaxf(k0.x + q0.x, 0.f) * w4.x; s01 += fmaxf(k0.x + q1.x, 0.f) * w4.x;
            s10 += fmaxf(k1.x + q0.x, 0.f) * w4.x; s11 += fmaxf(k1.x + q1.x, 0.f) * w4.x;
            s00 += fmaxf(k0.y + q0.y, 0.f) * w4.y; s01 += fmaxf(k0.y + q1.y, 0.f) * w4.y;
            s10 += fmaxf(k1.y + q0.y, 0.f) * w4.y; s11 += fmaxf(k1.y + q1.y, 0.f) * w4.y;
            s00 += fmaxf(k0.z + q0.z, 0.f) * w4.z; s01 += fmaxf(k0.z + q1.z, 0.f) * w4.z;
            s10 += fmaxf(k1.z + q0.z, 0.f) * w4.z; s11 += fmaxf(k1.z + q1.z, 0.f) * w4.z;
            s00 += fmaxf(k0.w + q0.w, 0.f) * w4.w; s01 += fmaxf(k0.w + q1.w, 0.f) * w4.w;
            s10 += fmaxf(k1.w + q0.w, 0.f) * w4.w; s11 += fmaxf(k1.w + q1.w, 0.f) * w4.w;
        }
        // diagonal mask: global i == global j
        int di = (it * 32 + ty * 2) - (jt * 32 + tx * 2);
        if (di == 0)  { s00 -= 10000.f; s11 -= 10000.f; }
        if (di == 1)  { s10 -= 10000.f; }
        if (di == -1) { s01 -= 10000.f; }

        w_s[tx * 2 + 0][ty * 2 + 0] = fast_sigmoid(s00);
        w_s[tx * 2 + 1][ty * 2 + 0] = fast_sigmoid(s01);
        w_s[tx * 2 + 0][ty * 2 + 1] = fast_sigmoid(s10);
        w_s[tx * 2 + 1][ty * 2 + 1] = fast_sigmoid(s11);
        __syncthreads();

        // ---- wv accumulate (f32x2) ----
        #pragma unroll
        for (int kk = 0; kk < 32; kk++) {
            float w0f = w_s[kk][ty * 2 + 0];
            float w1f = w_s[kk][ty * 2 + 1];
            unsigned long long wp0 = pack2(w0f, w0f);
            unsigned long long wp1 = pack2(w1f, w1f);
            float4 va = *(const float4*)&v_s[kk][tx * 4];
            float4 vb = *(const float4*)&v_s[kk][64 + tx * 4];
            unsigned long long v0 = pack2(va.x, va.y);
            unsigned long long v1 = pack2(va.z, va.w);
            unsigned long long v2 = pack2(vb.x, vb.y);
            unsigned long long v3 = pack2(vb.z, vb.w);
            acc2[0][0] = fma2(wp0, v0, acc2[0][0]);
            acc2[0][1] = fma2(wp0, v1, acc2[0][1]);
            acc2[0][2] = fma2(wp0, v2, acc2[0][2]);
            acc2[0][3] = fma2(wp0, v3, acc2[0][3]);
            acc2[1][0] = fma2(wp1, v0, acc2[1][0]);
            acc2[1][1] = fma2(wp1, v1, acc2[1][1]);
            acc2[1][2] = fma2(wp1, v2, acc2[1][2]);
            acc2[1][3] = fma2(wp1, v3, acc2[1][3]);
        }
    }

    // write out: rows mbase + ty*2 + ui, cols 128 + head*128 + {tx*4, 64+tx*4}
    #pragma unroll
    for (int ui = 0; ui < 2; ui++) {
        float* dst = cbuf + (size_t)(mbase + ty * 2 + ui) * 640 + 128 + head * 128;
        float o0, o1, o2, o3;
        unpack2(acc2[ui][0], o0, o1);
        unpack2(acc2[ui][1], o2, o3);
        *(float4*)(dst + tx * 4) = make_float4(o0, o1, o2, o3);
        unpack2(acc2[ui][2], o0, o1);
        unpack2(acc2[ui][3], o2, o3);
        *(float4*)(dst + 64 + tx * 4) = make_float4(o0, o1, o2, o3);
    }
}

// ---------------------------------------------------------------------------
// launch
// ---------------------------------------------------------------------------
extern "C" void kernel_launch(void* const* d_in, const int* in_sizes, int n_in,
                              void* d_out, int out_size)
{
    const float* x   = (const float*)d_in[0];
    const float* Wk  = (const float*)d_in[1];
    const float* bk  = (const float*)d_in[2];
    const float* Wq  = (const float*)d_in[3];
    const float* bq  = (const float*)d_in[4];
    const float* Wv  = (const float*)d_in[5];
    const float* bv  = (const float*)d_in[6];
    const float* Wa1 = (const float*)d_in[7];
    const float* ba1 = (const float*)d_in[8];
    const float* Wa2 = (const float*)d_in[9];
    const float* ba2 = (const float*)d_in[10];
    const float* Wd1 = (const float*)d_in[11];
    const float* bd1 = (const float*)d_in[12];
    const float* Wd2 = (const float*)d_in[13];
    const float* bd2 = (const float*)d_in[14];
    float* out = (float*)d_out;

    float *pWall, *pball, *phkq, *pc, *ph1;
    cudaGetSymbolAddress((void**)&pWall, g_Wall);
    cudaGetSymbolAddress((void**)&pball, g_ball);
    cudaGetSymbolAddress((void**)&phkq, g_hkq);
    cudaGetSymbolAddress((void**)&pc,   g_c);
    cudaGetSymbolAddress((void**)&ph1,  g_h1);

    // 1. fused effective weights [Uk|Uq|Wv] + biases
    prep_kernel<<<16, 256>>>(Wk, bk, Wq, bq, Wv, bv, Wa1, ba1);

    // 2. [hk|hq|v] = x @ Wall + ball   (M=2048, N=384, K=128)
    //    cols [0,256) -> g_hkq (ld 256), cols [256,384) -> g_c cols [0,128) (ld 640)
    gemm64<false><<<dim3(6, 32), 256>>>(x, 128, pWall, 384, pball,
                                        phkq, 256, pc, 640, 256, 128);

    // 3. attention: writes g_c cols [128, 640)
    attn_kernel<<<dim3(32, 4, 2), 256>>>(phkq, pc, Wa2, ba2);

    // 4. h1 = relu(c @ Wd1 + bd1)      (M=2048, N=256, K=640)
    gemm64<true><<<dim3(4, 32), 256>>>(pc, 640, Wd1, 256, bd1,
                                       ph1, 256, ph1, 256, 1 << 30, 640);

    // 5. out = h1 @ Wd2 + bd2          (M=2048, N=128, K=256)
    gemm64<false><<<dim3(2, 32), 256>>>(ph1, 256, Wd2, 128, bd2,
                                        out, 128, out, 128, 1 << 30, 256);
}

// round 3
// speedup vs baseline: 4.4389x; 1.3974x over previous
#include <cuda_runtime.h>
#include <stdint.h>

typedef unsigned long long ull;

// ---------------------------------------------------------------------------
// Scratch (device globals — no allocation allowed)
// ---------------------------------------------------------------------------
__device__ float g_Wall[128 * 384];   // [Uk | Uq | Wv]  rna-rounded to tf32
__device__ float g_ball[384];         // [ck+ba1 | cq | bv]  fp32
__device__ float g_Wd1r[640 * 256];   // Wd1 rna-rounded
__device__ float g_Wd2r[256 * 128];   // Wd2 rna-rounded
__device__ float g_hkq[2048 * 256];   // [hk | hq] per row (fp32 accum of tf32 mma)
__device__ float g_c[2048 * 640];     // concat [v | o0..o3]  (tf32-rounded values)
__device__ float g_h1[2048 * 256];    // decoder hidden (tf32-rounded)

// ---------------------------------------------------------------------------
// helpers
// ---------------------------------------------------------------------------
__device__ __forceinline__ ull pack2(float lo, float hi) {
    ull r; asm("mov.b64 %0, {%1, %2};" : "=l"(r) : "f"(lo), "f"(hi)); return r;
}
__device__ __forceinline__ void unpack2(ull v, float& lo, float& hi) {
    asm("mov.b64 {%0, %1}, %2;" : "=f"(lo), "=f"(hi) : "l"(v));
}
__device__ __forceinline__ ull fma2(ull a, ull b, ull c) {
    ull d; asm("fma.rn.f32x2 %0, %1, %2, %3;" : "=l"(d) : "l"(a), "l"(b), "l"(c)); return d;
}
__device__ __forceinline__ ull add2(ull a, ull b) {
    ull d; asm("add.rn.f32x2 %0, %1, %2;" : "=l"(d) : "l"(a), "l"(b)); return d;
}
__device__ __forceinline__ float rna_tf32(float x) {
    uint32_t r; asm("cvt.rna.tf32.f32 %0, %1;" : "=r"(r) : "f"(x));
    return __uint_as_float(r);
}
__device__ __forceinline__ float fast_sigmoid(float s) {
    float e = __expf(-s);
    float d = 1.f + e, r;
    asm("rcp.approx.f32 %0, %1;" : "=f"(r) : "f"(d));
    return r;
}
__device__ __forceinline__ void mma_tf32(float c[4],
    uint32_t a0, uint32_t a1, uint32_t a2, uint32_t a3,
    uint32_t b0, uint32_t b1)
{
    asm("mma.sync.aligned.m16n8k8.row.col.f32.tf32.tf32.f32 "
        "{%0,%1,%2,%3},{%4,%5,%6,%7},{%8,%9},{%0,%1,%2,%3};"
        : "+f"(c[0]), "+f"(c[1]), "+f"(c[2]), "+f"(c[3])
        : "r"(a0), "r"(a1), "r"(a2), "r"(a3), "r"(b0), "r"(b1));
}
__device__ __forceinline__ uint32_t fu(float x) { return __float_as_uint(x); }

// ---------------------------------------------------------------------------
// prep: build [Uk|Uq|Wv] (rna-rounded), fused bias, rounded decoder weights.
// ---------------------------------------------------------------------------
__global__ __launch_bounds__(256) void prep_kernel(
    const float* __restrict__ Wk, const float* __restrict__ bk,
    const float* __restrict__ Wq, const float* __restrict__ bq,
    const float* __restrict__ Wv, const float* __restrict__ bv,
    const float* __restrict__ Wa1, const float* __restrict__ ba1,
    const float* __restrict__ Wd1, const float* __restrict__ Wd2)
{
    __shared__ float wa[64 * 32];
    int tid = threadIdx.x;
    for (int i = tid; i < 64 * 32; i += 256) wa[i] = Wa1[i];
    __syncthreads();

    int stride = gridDim.x * 256;
    for (int idx = blockIdx.x * 256 + tid; idx < 128 * 128; idx += stride) {
        int d = idx >> 7, j = idx & 127;
        int hb = j & ~31, a = j & 31;
        float sk = 0.f, sq = 0.f;
        #pragma unroll
        for (int t = 0; t < 32; t++) {
            sk += Wk[d * 128 + hb + t] * wa[t * 32 + a];
            sq += Wq[d * 128 + hb + t] * wa[(32 + t) * 32 + a];
        }
        g_Wall[d * 384 + j]       = rna_tf32(sk);
        g_Wall[d * 384 + 128 + j] = rna_tf32(sq);
        g_Wall[d * 384 + 256 + j] = rna_tf32(Wv[d * 128 + j]);
    }
    for (int idx = blockIdx.x * 256 + tid; idx < 640 * 256; idx += stride)
        g_Wd1r[idx] = rna_tf32(Wd1[idx]);
    for (int idx = blockIdx.x * 256 + tid; idx < 256 * 128; idx += stride)
        g_Wd2r[idx] = rna_tf32(Wd2[idx]);
    if (blockIdx.x == 0 && tid < 128) {
        int hb = tid & ~31, a = tid & 31;
        float sk = 0.f, sq = 0.f;
        #pragma unroll
        for (int t = 0; t < 32; t++) {
            sk += bk[hb + t] * wa[t * 32 + a];
            sq += bq[hb + t] * wa[(32 + t) * 32 + a];
        }
        g_ball[tid]       = sk + ba1[a];   // ba1 folded into hk bias
        g_ball[128 + tid] = sq;
        g_ball[256 + tid] = bv[tid];
    }
}

// ---------------------------------------------------------------------------
// tf32 mma GEMM: C = act(A @ W + bias).
// Block tile 64x64, K-chunk 32, 256 threads (8 warps: 2m x 4n), warp m32n16.
// Column router: n < nsplit -> C1/ldc1 (round if rnd1), else C2/ldc2 (rnd2).
// ---------------------------------------------------------------------------
template <bool RELU>
__global__ __launch_bounds__(256, 2) void gemm_mma(
    const float* __restrict__ A, int lda,
    const float* __restrict__ W, int ldw,
    const float* __restrict__ bias,
    float* __restrict__ C1, int ldc1, bool rnd1,
    float* __restrict__ C2, int ldc2, bool rnd2, int nsplit,
    int K)
{
    // permuted k layout: element k of a 32-chunk lives at col ((k&7)<<2)|(k>>3)
    __shared__ float As[2][64][36];   // [m][kperm]
    __shared__ float Bs[2][64][36];   // [n][kperm]

    int tid = threadIdx.x;
    int lane = tid & 31, wq = tid >> 5;
    int wm = wq >> 2, wn = wq & 3;          // warp grid 2m x 4n
    int r = lane >> 2, c4 = lane & 3;
    int m0 = blockIdx.y * 64, n0 = blockIdx.x * 64;

    float acc[2][2][4];
    #pragma unroll
    for (int i = 0; i < 2; i++)
        #pragma unroll
        for (int j = 0; j < 2; j++)
            #pragma unroll
            for (int e = 0; e < 4; e++) acc[i][j][e] = 0.f;

    int nchunks = K >> 5;

    // chunk loader: LDG float4 -> scattered STS (k-permuted)
    auto load_chunk = [&](int ck, int buf) {
        int k0 = ck << 5;
        #pragma unroll
        for (int s = 0; s < 2; s++) {
            int lin = tid + s * 256;                 // A: 64x32 = 512 float4
            int rr = lin >> 3, cc = lin & 7;
            float4 f = *(const float4*)(A + (size_t)(m0 + rr) * lda + k0 + cc * 4);
            float v[4] = {f.x, f.y, f.z, f.w};
            #pragma unroll
            for (int e = 0; e < 4; e++) {
                int k = cc * 4 + e;
                As[buf][rr][((k & 7) << 2) | (k >> 3)] = v[e];
            }
        }
        #pragma unroll
        for (int s = 0; s < 2; s++) {
            int lin = tid + s * 256;                 // W: 32x64 = 512 float4
            int kr = lin >> 4, n4 = lin & 15;
            float4 f = *(const float4*)(W + (size_t)(k0 + kr) * ldw + n0 + n4 * 4);
            float v[4] = {f.x, f.y, f.z, f.w};
            int pc = ((kr & 7) << 2) | (kr >> 3);
            #pragma unroll
            for (int e = 0; e < 4; e++)
                Bs[buf][n4 * 4 + e][pc] = v[e];
        }
    };

    load_chunk(0, 0);
    __syncthreads();

    for (int ck = 0; ck < nchunks; ck++) {
        int p = ck & 1;
        // fragments
        float4 aLo[2], aL8[2], aHi[2], aH8[2];
        #pragma unroll
        for (int mt = 0; mt < 2; mt++) {
            int rb = wm * 32 + mt * 16 + r;
            aLo[mt] = *(const float4*)&As[p][rb][c4 * 4];
            aL8[mt] = *(const float4*)&As[p][rb + 8][c4 * 4];
            aHi[mt] = *(const float4*)&As[p][rb][(c4 + 4) * 4];
            aH8[mt] = *(const float4*)&As[p][rb + 8][(c4 + 4) * 4];
        }
        float4 b0v[2], b1v[2];
        #pragma unroll
        for (int nt = 0; nt < 2; nt++) {
            int nb = wn * 16 + nt * 8 + r;
            b0v[nt] = *(const float4*)&Bs[p][nb][c4 * 4];
            b1v[nt] = *(const float4*)&Bs[p][nb][(c4 + 4) * 4];
        }
        #pragma unroll
        for (int kt = 0; kt < 4; kt++) {
            #pragma unroll
            for (int mt = 0; mt < 2; mt++) {
                float a0 = ((const float*)&aLo[mt])[kt];
                float a1 = ((const float*)&aL8[mt])[kt];
                float a2 = ((const float*)&aHi[mt])[kt];
                float a3 = ((const float*)&aH8[mt])[kt];
                #pragma unroll
                for (int nt = 0; nt < 2; nt++) {
                    float b0 = ((const float*)&b0v[nt])[kt];
                    float b1 = ((const float*)&b1v[nt])[kt];
                    mma_tf32(acc[mt][nt], fu(a0), fu(a1), fu(a2), fu(a3),
                             fu(b0), fu(b1));
                }
            }
        }
        if (ck + 1 < nchunks) load_chunk(ck + 1, 1 - p);
        __syncthreads();
    }

    // epilogue
    bool left = (n0 < nsplit);
    float* Cb = left ? (C1 + n0) : (C2 + (n0 - nsplit));
    int ldc = left ? ldc1 : ldc2;
    bool rnd = left ? rnd1 : rnd2;

    #pragma unroll
    for (int mt = 0; mt < 2; mt++) {
        #pragma unroll
        for (int nt = 0; nt < 2; nt++) {
            int row = m0 + wm * 32 + mt * 16 + r;
            int col = wn * 16 + nt * 8 + 2 * c4;
            float2 bb = *(const float2*)(bias + n0 + col);
            float o0 = acc[mt][nt][0] + bb.x, o1 = acc[mt][nt][1] + bb.y;
            float o2 = acc[mt][nt][2] + bb.x, o3 = acc[mt][nt][3] + bb.y;
            if (RELU) {
                o0 = fmaxf(o0, 0.f); o1 = fmaxf(o1, 0.f);
                o2 = fmaxf(o2, 0.f); o3 = fmaxf(o3, 0.f);
            }
            if (rnd) {
                o0 = rna_tf32(o0); o1 = rna_tf32(o1);
                o2 = rna_tf32(o2); o3 = rna_tf32(o3);
            }
            *(float2*)(Cb + (size_t)row * ldc + col) = make_float2(o0, o1);
            *(float2*)(Cb + (size_t)(row + 8) * ldc + col) = make_float2(o2, o3);
        }
    }
}

// ---------------------------------------------------------------------------
// Attention: block = (32 i-rows, head, batch), grid (32,4,2).
// Scores scalar fp32 (f32x2-packed, exact relu identity), wv via tf32 mma.
// ---------------------------------------------------------------------------
__global__ __launch_bounds__(256, 2) void attn_kernel(
    const float* __restrict__ hkq,
    float* __restrict__ cbuf,
    const float* __restrict__ Wa2,
    const float* __restrict__ ba2)
{
    __shared__ float hk_s[32][36];
    __shared__ float hq_s[32][36];
    __shared__ float v_s[2][32][136];   // padded 136: conflict-free B frags
    __shared__ float w_s[32][36];       // [i][jperm]
    __shared__ float wa2h[32];

    int tid = threadIdx.x;
    int lane = tid & 31, wq = tid >> 5;
    int tx = tid & 15, ty = tid >> 4;
    int it = blockIdx.x, head = blockIdx.y, bb = blockIdx.z;
    int mbase = bb * 1024 + it * 32;

    if (tid < 32) wa2h[tid] = 0.5f * Wa2[tid];
    {   // hk tile (resident all jt)
        int i = tid & 31, a4 = tid >> 5;
        float4 f = *(const float4*)(hkq + (size_t)(mbase + i) * 256 + head * 32 + a4 * 4);
        *(float4*)&hk_s[i][a4 * 4] = f;
    }
    {   // jt=0 hq + v
        int j = tid & 31, a4 = tid >> 5;
        float4 f = *(const float4*)(hkq + (size_t)(bb * 1024 + j) * 256 + 128 + head * 32 + a4 * 4);
        *(float4*)&hq_s[j][a4 * 4] = f;
        #pragma unroll
        for (int s = 0; s < 4; s++) {
            int lin = tid + s * 256;
            int jj = lin >> 5, d4 = lin & 31;
            float4 g = *(const float4*)(cbuf + (size_t)(bb * 1024 + jj) * 640 + d4 * 4);
            *(float4*)&v_s[0][jj][d4 * 4] = g;
        }
    }
    __syncthreads();

    float ba2v = ba2[0];
    float acc[2][2][4];
    #pragma unroll
    for (int i = 0; i < 2; i++)
        #pragma unroll
        for (int j = 0; j < 2; j++)
            #pragma unroll
            for (int e = 0; e < 4; e++) acc[i][j][e] = 0.f;

    int i0 = ty * 2, j0 = tx * 2;
    const ull ABSM = 0x7FFFFFFF7FFFFFFFULL;

    for (int jt = 0; jt < 32; jt++) {
        int p = jt & 1;

        // prefetch next j-tile into regs
        float4 nhq; float4 nv[4];
        if (jt < 31) {
            int jn = bb * 1024 + (jt + 1) * 32;
            nhq = *(const float4*)(hkq + (size_t)(jn + (tid & 31)) * 256 + 128 + head * 32 + (tid >> 5) * 4);
            #pragma unroll
            for (int s = 0; s < 4; s++) {
                int lin = tid + s * 256;
                nv[s] = *(const float4*)(cbuf + (size_t)(jn + (lin >> 5)) * 640 + (lin & 31) * 4);
            }
        }

        // ---- scores (2i x 2j), f32x2-packed exact relu: relu(u)*w = (u+|u|)*(w/2)
        ull s2[4][2];
        #pragma unroll
        for (int c = 0; c < 4; c++) { s2[c][0] = 0ULL; s2[c][1] = 0ULL; }
        #pragma unroll
        for (int a4 = 0; a4 < 8; a4++) {
            float4 kA = *(const float4*)&hk_s[i0][a4 * 4];
            float4 kB = *(const float4*)&hk_s[i0 + 1][a4 * 4];
            float4 qA = *(const float4*)&hq_s[j0][a4 * 4];
            float4 qB = *(const float4*)&hq_s[j0 + 1][a4 * 4];
            float4 wh = *(const float4*)&wa2h[a4 * 4];
            ull whp0 = pack2(wh.x, wh.y), whp1 = pack2(wh.z, wh.w);
            ull kA0 = pack2(kA.x, kA.y), kA1 = pack2(kA.z, kA.w);
            ull kB0 = pack2(kB.x, kB.y), kB1 = pack2(kB.z, kB.w);
            ull qA0 = pack2(qA.x, qA.y), qA1 = pack2(qA.z, qA.w);
            ull qB0 = pack2(qB.x, qB.y), qB1 = pack2(qB.z, qB.w);
            #define SCOMBO(kp0, kp1, qp0, qp1, c) { \
                ull u0 = add2(kp0, qp0), u1 = add2(kp1, qp1); \
                ull t0 = add2(u0, u0 & ABSM); \
                ull t1 = add2(u1, u1 & ABSM); \
                s2[c][0] = fma2(t0, whp0, s2[c][0]); \
                s2[c][1] = fma2(t1, whp1, s2[c][1]); }
            SCOMBO(kA0, kA1, qA0, qA1, 0)
            SCOMBO(kA0, kA1, qB0, qB1, 1)
            SCOMBO(kB0, kB1, qA0, qA1, 2)
            SCOMBO(kB0, kB1, qB0, qB1, 3)
            #undef SCOMBO
        }
        float sc[4];
        #pragma unroll
        for (int c = 0; c < 4; c++) {
            float f0, f1, f2, f3;
            unpack2(s2[c][0], f0, f1);
            unpack2(s2[c][1], f2, f3);
            sc[c] = ba2v + ((f0 + f1) + (f2 + f3));
        }
        // diagonal mask (i0,j0 even => only di==0 combos can hit diag)
        int di = (it * 32 + i0) - (jt * 32 + j0);
        if (di == 0) { sc[0] -= 10000.f; sc[3] -= 10000.f; }

        // sigmoid -> rna -> w_s[i][jperm]
        #pragma unroll
        for (int c = 0; c < 4; c++) {
            int ii = i0 + (c >> 1), jj = j0 + (c & 1);
            w_s[ii][((jj & 7) << 2) | (jj >> 3)] = rna_tf32(fast_sigmoid(sc[c]));
        }
        __syncthreads();   // w ready; score reads of hq_s done

        // ---- wv mma: warp wq owns d-cols [wq*16, wq*16+16)
        {
            int r = lane >> 2, c4 = lane & 3;
            int n0 = wq * 16;
            float4 aLo[2], aL8[2], aHi[2], aH8[2];
            #pragma unroll
            for (int mt = 0; mt < 2; mt++) {
                int rb = mt * 16 + r;
                aLo[mt] = *(const float4*)&w_s[rb][c4 * 4];
                aL8[mt] = *(const float4*)&w_s[rb + 8][c4 * 4];
                aHi[mt] = *(const float4*)&w_s[rb][(c4 + 4) * 4];
                aH8[mt] = *(const float4*)&w_s[rb + 8][(c4 + 4) * 4];
            }
            #pragma unroll
            for (int kt = 0; kt < 4; kt++) {
                #pragma unroll
                for (int mt = 0; mt < 2; mt++) {
                    float a0 = ((const float*)&aLo[mt])[kt];
                    float a1 = ((const float*)&aL8[mt])[kt];
                    float a2 = ((const float*)&aHi[mt])[kt];
                    float a3 = ((const float*)&aH8[mt])[kt];
                    #pragma unroll
                    for (int nt = 0; nt < 2; nt++) {
                        float b0 = v_s[p][kt * 8 + c4][n0 + nt * 8 + r];
                        float b1 = v_s[p][kt * 8 + c4 + 4][n0 + nt * 8 + r];
                        mma_tf32(acc[mt][nt], fu(a0), fu(a1), fu(a2), fu(a3),
                                 fu(b0), fu(b1));
                    }
                }
            }
        }

        // store prefetched tiles (hq single-buffer: safe, score reads done)
        if (jt < 31) {
            *(float4*)&hq_s[tid & 31][(tid >> 5) * 4] = nhq;
            #pragma unroll
            for (int s = 0; s < 4; s++) {
                int lin = tid + s * 256;
                *(float4*)&v_s[1 - p][lin >> 5][(lin & 31) * 4] = nv[s];
            }
        }
        __syncthreads();
    }

    // epilogue: rna-rounded (feeds tf32 decoder)
    {
        int r = lane >> 2, c4 = lane & 3;
        #pragma unroll
        for (int mt = 0; mt < 2; mt++) {
            #pragma unroll
            for (int nt = 0; nt < 2; nt++) {
                int row = mbase + mt * 16 + r;
                int col = 128 + head * 128 + wq * 16 + nt * 8 + 2 * c4;
                *(float2*)(cbuf + (size_t)row * 640 + col) =
                    make_float2(rna_tf32(acc[mt][nt][0]), rna_tf32(acc[mt][nt][1]));
                *(float2*)(cbuf + (size_t)(row + 8) * 640 + col) =
                    make_float2(rna_tf32(acc[mt][nt][2]), rna_tf32(acc[mt][nt][3]));
            }
        }
    }
}

// ---------------------------------------------------------------------------
// launch
// ---------------------------------------------------------------------------
extern "C" void kernel_launch(void* const* d_in, const int* in_sizes, int n_in,
                              void* d_out, int out_size)
{
    const float* x   = (const float*)d_in[0];
    const float* Wk  = (const float*)d_in[1];
    const float* bk  = (const float*)d_in[2];
    const float* Wq  = (const float*)d_in[3];
    const float* bq  = (const float*)d_in[4];
    const float* Wv  = (const float*)d_in[5];
    const float* bv  = (const float*)d_in[6];
    const float* Wa1 = (const float*)d_in[7];
    const float* ba1 = (const float*)d_in[8];
    const float* Wa2 = (const float*)d_in[9];
    const float* ba2 = (const float*)d_in[10];
    const float* Wd1 = (const float*)d_in[11];
    const float* bd1 = (const float*)d_in[12];
    const float* Wd2 = (const float*)d_in[13];
    const float* bd2 = (const float*)d_in[14];
    float* out = (float*)d_out;

    float *pWall, *pball, *pWd1r, *pWd2r, *phkq, *pc, *ph1;
    cudaGetSymbolAddress((void**)&pWall, g_Wall);
    cudaGetSymbolAddress((void**)&pball, g_ball);
    cudaGetSymbolAddress((void**)&pWd1r, g_Wd1r);
    cudaGetSymbolAddress((void**)&pWd2r, g_Wd2r);
    cudaGetSymbolAddress((void**)&phkq, g_hkq);
    cudaGetSymbolAddress((void**)&pc,   g_c);
    cudaGetSymbolAddress((void**)&ph1,  g_h1);

    // 1. fused effective weights + rounded decoder weights
    prep_kernel<<<32, 256>>>(Wk, bk, Wq, bq, Wv, bv, Wa1, ba1, Wd1, Wd2);

    // 2. [hk|hq|v] = x @ Wall + ball   (M=2048, N=384, K=128)
    //    cols [0,256) -> g_hkq (no rounding: feeds fp32 scores)
    //    cols [256,384) -> g_c cols [0,128) rounded (feeds tf32 mma)
    gemm_mma<false><<<dim3(6, 32), 256>>>(x, 128, pWall, 384, pball,
                                          phkq, 256, false,
                                          pc, 640, true, 256, 128);

    // 3. attention: writes g_c cols [128, 640) rounded
    attn_kernel<<<dim3(32, 4, 2), 256>>>(phkq, pc, Wa2, ba2);

    // 4. h1 = relu(c @ Wd1 + bd1)      (M=2048, N=256, K=640), rounded
    gemm_mma<true><<<dim3(4, 32), 256>>>(pc, 640, pWd1r, 256, bd1,
                                         ph1, 256, true,
                                         ph1, 256, true, 1 << 30, 640);

    // 5. out = h1 @ Wd2 + bd2          (M=2048, N=128, K=256)
    gemm_mma<false><<<dim3(2, 32), 256>>>(ph1, 256, pWd2r, 128, bd2,
                                          out, 128, false,
                                          out, 128, false, 1 << 30, 256);
}